// round 1
// baseline (speedup 1.0000x reference)
#include <cuda_runtime.h>

#define BATCH 8
#define SEQ 2048
#define HID 512
#define HD 64
#define CHUNKSZ 256

// log2(0.96875) to double precision, rounded to fp32
#define LOG2_GAMMA (-0.04580368961312478f)

// Scratch for Q, K, V (fp32), 4 MB each — device globals (no allocation allowed)
__device__ float g_Q[BATCH * SEQ * HD];
__device__ float g_K[BATCH * SEQ * HD];
__device__ float g_V[BATCH * SEQ * HD];

// ---------------------------------------------------------------------------
// Kernel A: fused QKV projection + xPos rotary epilogue.
// grid = (SEQ/128, BATCH, 3), block = 256 threads.
// Output tile: 128 rows x 64 cols. Per-thread: 8 rows x 4 cols.
// Column mapping per thread: {2tx, 2tx+1, 2tx+32, 2tx+33} so each rotary
// (even,odd) pair lives in one thread.
// Dynamic smem: Xs[128][65] + Ws[64][65]
// ---------------------------------------------------------------------------
__global__ void qkv_kernel(const float* __restrict__ X,
                           const float* __restrict__ WQ,
                           const float* __restrict__ WK,
                           const float* __restrict__ WV) {
    extern __shared__ float sm[];
    float* Xs = sm;               // [128][65]
    float* Ws = sm + 128 * 65;    // [64][65]

    const int g    = blockIdx.z;          // 0=Q, 1=K, 2=V
    const int b    = blockIdx.y;
    const int row0 = blockIdx.x * 128;
    const int tid  = threadIdx.x;
    const int tx   = tid & 15;
    const int ty   = tid >> 4;

    const float* W = (g == 0) ? WQ : ((g == 1) ? WK : WV);

    float acc[8][4];
#pragma unroll
    for (int i = 0; i < 8; i++)
#pragma unroll
        for (int j = 0; j < 4; j++) acc[i][j] = 0.0f;

    for (int k0 = 0; k0 < HID; k0 += 64) {
        // Load X tile: 128 rows x 64 k-cols (float4, coalesced)
        const float4* X4 = (const float4*)(X + (size_t)(b * SEQ + row0) * HID + k0);
        for (int idx = tid; idx < 128 * 16; idx += 256) {
            int r = idx >> 4, c4 = idx & 15;
            float4 v = X4[r * (HID / 4) + c4];
            float* d = &Xs[r * 65 + c4 * 4];
            d[0] = v.x; d[1] = v.y; d[2] = v.z; d[3] = v.w;
        }
        // Load W tile: 64 k-rows x 64 cols
        const float4* W4 = (const float4*)(W + (size_t)k0 * HD);
        for (int idx = tid; idx < 64 * 16; idx += 256) {
            int r = idx >> 4, c4 = idx & 15;
            float4 v = W4[r * (HD / 4) + c4];
            float* d = &Ws[r * 65 + c4 * 4];
            d[0] = v.x; d[1] = v.y; d[2] = v.z; d[3] = v.w;
        }
        __syncthreads();

#pragma unroll 8
        for (int kk = 0; kk < 64; kk++) {
            const float w0 = Ws[kk * 65 + 2 * tx];
            const float w1 = Ws[kk * 65 + 2 * tx + 1];
            const float w2 = Ws[kk * 65 + 2 * tx + 32];
            const float w3 = Ws[kk * 65 + 2 * tx + 33];
#pragma unroll
            for (int i = 0; i < 8; i++) {
                const float xv = Xs[(ty + 16 * i) * 65 + kk];
                acc[i][0] += xv * w0;
                acc[i][1] += xv * w1;
                acc[i][2] += xv * w2;
                acc[i][3] += xv * w3;
            }
        }
        __syncthreads();
    }

    // Epilogue: xPos for Q/K, passthrough for V.
    float* out = (g == 0) ? g_Q : ((g == 1) ? g_K : g_V);
#pragma unroll
    for (int i = 0; i < 8; i++) {
        const int l = row0 + ty + 16 * i;
        float* orow = out + (size_t)(b * SEQ + l) * HD;
        if (g == 2) {
            orow[2 * tx]      = acc[i][0];
            orow[2 * tx + 1]  = acc[i][1];
            orow[2 * tx + 32] = acc[i][2];
            orow[2 * tx + 33] = acc[i][3];
        } else {
            float pw = (float)l * (1.0f / 512.0f);
            if (g == 1) pw = -pw;   // K uses 1/scale
#pragma unroll
            for (int half = 0; half < 2; half++) {
                const int p = tx + 16 * half;               // pair index 0..31
                const float xe = acc[i][2 * half];
                const float xo = acc[i][2 * half + 1];
                const float sv = (2.0f * (float)p + 25.6f) * (1.0f / 89.6f);
                const float s  = powf(sv, pw);
                const float invf = powf(10000.0f, -(float)p * (1.0f / 32.0f));
                const float ang  = (float)l * invf;
                float si, co;
                sincosf(ang, &si, &co);
                si *= s; co *= s;
                orow[2 * p]     = xe * co - xo * si;
                orow[2 * p + 1] = xo * co + xe * si;
            }
        }
    }
}

// ---------------------------------------------------------------------------
// Kernel B: retention  O[i,:] = sum_{j < chunk_end(i)} (Q[i].K[j]) g^|i-j| V[j]
// grid = (SEQ/64 = 32 q-tiles, BATCH), block = 256 threads.
// Each block: 64 queries; iterates (chunk+1)*4 valid 64-wide j-tiles.
// Per-thread: rows {ty, ty+16, ty+32, ty+48}, cols {tx, tx+16, tx+32, tx+48}.
// Dynamic smem: Qs/Ks/Vs/Ps each [64][65].
// ---------------------------------------------------------------------------
__global__ void retention_kernel(float* __restrict__ out) {
    extern __shared__ float sm[];
    float* Qs = sm;                 // [64][65]
    float* Ks = Qs + 64 * 65;
    float* Vs = Ks + 64 * 65;
    float* Ps = Vs + 64 * 65;

    const int b     = blockIdx.y;
    const int qbase = blockIdx.x * 64;
    const int chunk = qbase / CHUNKSZ;
    const int jtiles = (chunk + 1) * (CHUNKSZ / 64);
    const int tid = threadIdx.x;
    const int tx  = tid & 15;
    const int ty  = tid >> 4;

    // Load Q tile once
    {
        const float4* Q4 = (const float4*)(g_Q + (size_t)(b * SEQ + qbase) * HD);
        for (int idx = tid; idx < 64 * 16; idx += 256) {
            int r = idx >> 4, c4 = idx & 15;
            float4 v = Q4[r * (HD / 4) + c4];
            float* d = &Qs[r * 65 + c4 * 4];
            d[0] = v.x; d[1] = v.y; d[2] = v.z; d[3] = v.w;
        }
    }

    float o[4][4];
#pragma unroll
    for (int i = 0; i < 4; i++)
#pragma unroll
        for (int j = 0; j < 4; j++) o[i][j] = 0.0f;

    for (int jt = 0; jt < jtiles; jt++) {
        const int j0 = jt * 64;
        __syncthreads();   // protect Ks/Vs from previous stage-2 readers

        // Load K,V tiles 64x64
        const float4* K4 = (const float4*)(g_K + (size_t)(b * SEQ + j0) * HD);
        const float4* V4 = (const float4*)(g_V + (size_t)(b * SEQ + j0) * HD);
        for (int idx = tid; idx < 64 * 16; idx += 256) {
            int r = idx >> 4, c4 = idx & 15;
            float4 v = K4[r * (HD / 4) + c4];
            float* d = &Ks[r * 65 + c4 * 4];
            d[0] = v.x; d[1] = v.y; d[2] = v.z; d[3] = v.w;
            v = V4[r * (HD / 4) + c4];
            d = &Vs[r * 65 + c4 * 4];
            d[0] = v.x; d[1] = v.y; d[2] = v.z; d[3] = v.w;
        }
        __syncthreads();

        // Stage 1: P = (Q K^T) * gamma^|i-j|
        float p[4][4];
#pragma unroll
        for (int i = 0; i < 4; i++)
#pragma unroll
            for (int j = 0; j < 4; j++) p[i][j] = 0.0f;

#pragma unroll 8
        for (int h = 0; h < 64; h++) {
            float qv[4], kv[4];
#pragma unroll
            for (int ii = 0; ii < 4; ii++) qv[ii] = Qs[(ty + 16 * ii) * 65 + h];
#pragma unroll
            for (int jj = 0; jj < 4; jj++) kv[jj] = Ks[(tx + 16 * jj) * 65 + h];
#pragma unroll
            for (int ii = 0; ii < 4; ii++)
#pragma unroll
                for (int jj = 0; jj < 4; jj++) p[ii][jj] += qv[ii] * kv[jj];
        }
#pragma unroll
        for (int ii = 0; ii < 4; ii++) {
            const int i = qbase + ty + 16 * ii;
#pragma unroll
            for (int jj = 0; jj < 4; jj++) {
                const int j = j0 + tx + 16 * jj;
                const float d = exp2f(LOG2_GAMMA * fabsf((float)(i - j)));
                Ps[(ty + 16 * ii) * 65 + tx + 16 * jj] = p[ii][jj] * d;
            }
        }
        __syncthreads();

        // Stage 2: O += P @ V
#pragma unroll 8
        for (int kj = 0; kj < 64; kj++) {
            float pv[4], vv[4];
#pragma unroll
            for (int ii = 0; ii < 4; ii++) pv[ii] = Ps[(ty + 16 * ii) * 65 + kj];
#pragma unroll
            for (int jj = 0; jj < 4; jj++) vv[jj] = Vs[kj * 65 + tx + 16 * jj];
#pragma unroll
            for (int ii = 0; ii < 4; ii++)
#pragma unroll
                for (int jj = 0; jj < 4; jj++) o[ii][jj] += pv[ii] * vv[jj];
        }
    }

    // Write output
#pragma unroll
    for (int ii = 0; ii < 4; ii++) {
        float* orow = out + (size_t)(b * SEQ + qbase + ty + 16 * ii) * HD;
#pragma unroll
        for (int jj = 0; jj < 4; jj++) {
            orow[tx + 16 * jj] = o[ii][jj];
        }
    }
}

// ---------------------------------------------------------------------------
extern "C" void kernel_launch(void* const* d_in, const int* in_sizes, int n_in,
                              void* d_out, int out_size) {
    const float* X  = (const float*)d_in[0];
    const float* WQ = (const float*)d_in[1];
    const float* WK = (const float*)d_in[2];
    const float* WV = (const float*)d_in[3];
    float* out = (float*)d_out;

    const size_t smA = (size_t)(128 * 65 + 64 * 65) * sizeof(float);   // 49920 B
    const size_t smB = (size_t)(4 * 64 * 65) * sizeof(float);          // 66560 B

    cudaFuncSetAttribute(qkv_kernel, cudaFuncAttributeMaxDynamicSharedMemorySize,
                         (int)smA);
    cudaFuncSetAttribute(retention_kernel, cudaFuncAttributeMaxDynamicSharedMemorySize,
                         (int)smB);

    dim3 gridA(SEQ / 128, BATCH, 3);
    qkv_kernel<<<gridA, 256, smA>>>(X, WQ, WK, WV);

    dim3 gridB(SEQ / 64, BATCH);
    retention_kernel<<<gridB, 256, smB>>>(out);
}

// round 2
// speedup vs baseline: 4.0845x; 4.0845x over previous
#include <cuda_runtime.h>

#define BATCH 8
#define SEQ 2048
#define HID 512
#define HD 64
#define CHUNKSZ 256
#define NCHUNK (SEQ / CHUNKSZ)      // 8

// log2(0.96875)
#define LOG2_GAMMA (-0.04580368961312478f)

// ---------------------------------------------------------------------------
// Device scratch (no allocation allowed)
// ---------------------------------------------------------------------------
__device__ float g_Q[BATCH * SEQ * HD];
__device__ float g_K[BATCH * SEQ * HD];
__device__ float g_V[BATCH * SEQ * HD];
__device__ float g_A[BATCH * NCHUNK * HD * HD];   // per-chunk summaries, [v][h]
__device__ float g_S[BATCH * NCHUNK * HD * HD];   // scanned states,      [v][h]
__device__ float g_tab[SEQ * 128];                // xPos tables: per l: cosQ[32] sinQ[32] cosK[32] sinK[32]

#define SMSTR 68   // smem row stride in floats (16B aligned, 17 coprime 32)

// ---------------------------------------------------------------------------
// Table kernel: accurate xPos factors, once per launch. 65536 threads.
// ---------------------------------------------------------------------------
__global__ void tab_kernel() {
    int tid = blockIdx.x * blockDim.x + threadIdx.x;   // 0..65535
    int l = tid >> 5;
    int p = tid & 31;
    float sv = (2.0f * (float)p + 0.4f * (float)HD) / (1.4f * (float)HD);
    float pw = (float)l * (1.0f / 512.0f);
    float s = powf(sv, pw);
    float invf = powf(10000.0f, -(float)p * (1.0f / 32.0f));
    float si, co;
    sincosf((float)l * invf, &si, &co);
    float* t = g_tab + l * 128;
    t[p]      = co * s;
    t[32 + p] = si * s;
    t[64 + p] = co / s;
    t[96 + p] = si / s;
}

// ---------------------------------------------------------------------------
// Kernel A: fused QKV projection + table-based xPos epilogue.
// grid = (SEQ/128, BATCH, 3), block 256. Tile 128x64, per-thread 8x4.
// smem: Xs[128][68] + Wt[64][68] (W transposed: Wt[col][k])
// ---------------------------------------------------------------------------
__global__ void __launch_bounds__(256, 3)
qkv_kernel(const float* __restrict__ X,
           const float* __restrict__ WQ,
           const float* __restrict__ WK,
           const float* __restrict__ WV) {
    extern __shared__ float sm[];
    float* Xs = sm;                    // [128][SMSTR]
    float* Wt = sm + 128 * SMSTR;      // [64][SMSTR]  (transposed)

    const int g    = blockIdx.z;
    const int b    = blockIdx.y;
    const int row0 = blockIdx.x * 128;
    const int tid  = threadIdx.x;
    const int tx   = tid & 15;
    const int ty   = tid >> 4;

    const float* W = (g == 0) ? WQ : ((g == 1) ? WK : WV);

    float acc[8][4];
#pragma unroll
    for (int i = 0; i < 8; i++)
#pragma unroll
        for (int j = 0; j < 4; j++) acc[i][j] = 0.0f;

    const int wg = tid & 15;   // c4 group for W transpose
    const int kg = tid >> 4;   // k quad group

    for (int k0 = 0; k0 < HID; k0 += 64) {
        __syncthreads();
        // X tile: 128 x 64, row-major, float4
        const float4* X4 = (const float4*)(X + (size_t)(b * SEQ + row0) * HID + k0);
        for (int idx = tid; idx < 128 * 16; idx += 256) {
            int r = idx >> 4, c4 = idx & 15;
            *(float4*)&Xs[r * SMSTR + c4 * 4] = X4[r * (HID / 4) + c4];
        }
        // W tile transposed: Wt[c][k], 4x4 block per thread
        {
            const float4* W4 = (const float4*)(W + (size_t)k0 * HD);
            float4 a0 = W4[(4 * kg + 0) * 16 + wg];
            float4 a1 = W4[(4 * kg + 1) * 16 + wg];
            float4 a2 = W4[(4 * kg + 2) * 16 + wg];
            float4 a3 = W4[(4 * kg + 3) * 16 + wg];
            *(float4*)&Wt[(4 * wg + 0) * SMSTR + 4 * kg] = make_float4(a0.x, a1.x, a2.x, a3.x);
            *(float4*)&Wt[(4 * wg + 1) * SMSTR + 4 * kg] = make_float4(a0.y, a1.y, a2.y, a3.y);
            *(float4*)&Wt[(4 * wg + 2) * SMSTR + 4 * kg] = make_float4(a0.z, a1.z, a2.z, a3.z);
            *(float4*)&Wt[(4 * wg + 3) * SMSTR + 4 * kg] = make_float4(a0.w, a1.w, a2.w, a3.w);
        }
        __syncthreads();

        for (int kk = 0; kk < 64; kk += 4) {
            float4 w0 = *(const float4*)&Wt[(2 * tx)      * SMSTR + kk];
            float4 w1 = *(const float4*)&Wt[(2 * tx + 1)  * SMSTR + kk];
            float4 w2 = *(const float4*)&Wt[(2 * tx + 32) * SMSTR + kk];
            float4 w3 = *(const float4*)&Wt[(2 * tx + 33) * SMSTR + kk];
#pragma unroll
            for (int i = 0; i < 8; i++) {
                float4 xv = *(const float4*)&Xs[(ty + 16 * i) * SMSTR + kk];
                acc[i][0] += xv.x * w0.x; acc[i][1] += xv.x * w1.x;
                acc[i][2] += xv.x * w2.x; acc[i][3] += xv.x * w3.x;
                acc[i][0] += xv.y * w0.y; acc[i][1] += xv.y * w1.y;
                acc[i][2] += xv.y * w2.y; acc[i][3] += xv.y * w3.y;
                acc[i][0] += xv.z * w0.z; acc[i][1] += xv.z * w1.z;
                acc[i][2] += xv.z * w2.z; acc[i][3] += xv.z * w3.z;
                acc[i][0] += xv.w * w0.w; acc[i][1] += xv.w * w1.w;
                acc[i][2] += xv.w * w2.w; acc[i][3] += xv.w * w3.w;
            }
        }
    }

    float* out = (g == 0) ? g_Q : ((g == 1) ? g_K : g_V);
#pragma unroll
    for (int i = 0; i < 8; i++) {
        const int l = row0 + ty + 16 * i;
        float* orow = out + (size_t)(b * SEQ + l) * HD;
        if (g == 2) {
            orow[2 * tx]      = acc[i][0];
            orow[2 * tx + 1]  = acc[i][1];
            orow[2 * tx + 32] = acc[i][2];
            orow[2 * tx + 33] = acc[i][3];
        } else {
            const float* t = g_tab + l * 128 + (g == 1 ? 64 : 0);
            // pair p0 = tx  -> cols 2tx, 2tx+1
            float c0 = t[tx],      s0 = t[32 + tx];
            // pair p1 = tx+16 -> cols 2tx+32, 2tx+33
            float c1 = t[tx + 16], s1 = t[48 + tx];
            orow[2 * tx]      = acc[i][0] * c0 - acc[i][1] * s0;
            orow[2 * tx + 1]  = acc[i][1] * c0 + acc[i][0] * s0;
            orow[2 * tx + 32] = acc[i][2] * c1 - acc[i][3] * s1;
            orow[2 * tx + 33] = acc[i][3] * c1 + acc[i][2] * s1;
        }
    }
}

// ---------------------------------------------------------------------------
// R1: per-chunk summary A_c[v][h] = sum_{j in chunk} gamma^(255-j_loc) K[j,h] V[j,v]
// grid = (NCHUNK, BATCH), block 256, per-thread 4x4.
// ---------------------------------------------------------------------------
__global__ void __launch_bounds__(256, 3)
r1_kernel() {
    extern __shared__ float sm[];
    float* Ks = sm;                 // [64][SMSTR], rows pre-scaled by decay
    float* Vs = sm + 64 * SMSTR;    // [64][SMSTR]

    const int c = blockIdx.x;
    const int b = blockIdx.y;
    const int tid = threadIdx.x;
    const int tx = tid & 15;
    const int ty = tid >> 4;

    float acc[4][4];
#pragma unroll
    for (int i = 0; i < 4; i++)
#pragma unroll
        for (int j = 0; j < 4; j++) acc[i][j] = 0.0f;

    for (int jt = 0; jt < 4; jt++) {
        const int j0 = c * CHUNKSZ + jt * 64;
        __syncthreads();
        const float4* K4 = (const float4*)(g_K + (size_t)(b * SEQ + j0) * HD);
        const float4* V4 = (const float4*)(g_V + (size_t)(b * SEQ + j0) * HD);
        for (int idx = tid; idx < 64 * 16; idx += 256) {
            int r = idx >> 4, c4 = idx & 15;
            float w = exp2f(LOG2_GAMMA * (float)(255 - (jt * 64 + r)));
            float4 kv = K4[r * 16 + c4];
            kv.x *= w; kv.y *= w; kv.z *= w; kv.w *= w;
            *(float4*)&Ks[r * SMSTR + c4 * 4] = kv;
            *(float4*)&Vs[r * SMSTR + c4 * 4] = V4[r * 16 + c4];
        }
        __syncthreads();

#pragma unroll 4
        for (int j = 0; j < 64; j++) {
            float kv[4], vv[4];
#pragma unroll
            for (int jj = 0; jj < 4; jj++) kv[jj] = Ks[j * SMSTR + tx + 16 * jj];
#pragma unroll
            for (int ii = 0; ii < 4; ii++) vv[ii] = Vs[j * SMSTR + ty + 16 * ii];
#pragma unroll
            for (int ii = 0; ii < 4; ii++)
#pragma unroll
                for (int jj = 0; jj < 4; jj++) acc[ii][jj] += vv[ii] * kv[jj];
        }
    }

    float* A = g_A + (size_t)(b * NCHUNK + c) * HD * HD;
#pragma unroll
    for (int ii = 0; ii < 4; ii++)
#pragma unroll
        for (int jj = 0; jj < 4; jj++)
            A[(ty + 16 * ii) * HD + tx + 16 * jj] = acc[ii][jj];
}

// ---------------------------------------------------------------------------
// R2: scan  S_0 = 0,  S_c = gamma^256 * S_{c-1} + A_{c-1}.  grid = BATCH.
// ---------------------------------------------------------------------------
__global__ void r2_kernel() {
    const int b = blockIdx.x;
    const int tid = threadIdx.x;
    const float g256 = exp2f(LOG2_GAMMA * 256.0f);

    float4 s[4];
#pragma unroll
    for (int u = 0; u < 4; u++) s[u] = make_float4(0.f, 0.f, 0.f, 0.f);

    for (int c = 0; c < NCHUNK; c++) {
        float4* Sd = (float4*)(g_S + (size_t)(b * NCHUNK + c) * HD * HD);
        const float4* Ad = (const float4*)(g_A + (size_t)(b * NCHUNK + c) * HD * HD);
#pragma unroll
        for (int u = 0; u < 4; u++) {
            Sd[tid * 4 + u] = s[u];
            float4 a = Ad[tid * 4 + u];
            s[u].x = g256 * s[u].x + a.x;
            s[u].y = g256 * s[u].y + a.y;
            s[u].z = g256 * s[u].z + a.z;
            s[u].w = g256 * s[u].w + a.w;
        }
    }
}

// ---------------------------------------------------------------------------
// R3: output. grid = (SEQ/64, BATCH), block 256, per-thread 4x4 of 64x64 tile.
//   cross:  O = gamma^(il+1) * Q @ S_c        (skip for chunk 0)
//   within: 4 j-tiles of own chunk, P = (Q K^T) * gamma^|i-j|, O += P @ V
// smem: Qs + B0(Ks / St) + Vt + Ps, each [64][SMSTR]
// ---------------------------------------------------------------------------
__global__ void __launch_bounds__(256, 3)
r3_kernel(float* __restrict__ out) {
    extern __shared__ float sm[];
    float* Qs = sm;
    float* B0 = sm + 64 * SMSTR;        // St for cross stage, then K tiles
    float* Vt = sm + 2 * 64 * SMSTR;    // V transposed: Vt[v][j]
    float* Ps = sm + 3 * 64 * SMSTR;

    const int b     = blockIdx.y;
    const int qbase = blockIdx.x * 64;
    const int chunk = qbase / CHUNKSZ;
    const int il0   = (blockIdx.x & 3) * 64;   // local row base within chunk
    const int tid = threadIdx.x;
    const int tx  = tid & 15;
    const int ty  = tid >> 4;
    const int wg  = tid & 15;   // v4 group for V transpose
    const int jg  = tid >> 4;   // j quad group

    // Load Q tile (row-major), and S_c (if any) into B0
    {
        const float4* Q4 = (const float4*)(g_Q + (size_t)(b * SEQ + qbase) * HD);
        for (int idx = tid; idx < 64 * 16; idx += 256) {
            int r = idx >> 4, c4 = idx & 15;
            *(float4*)&Qs[r * SMSTR + c4 * 4] = Q4[r * 16 + c4];
        }
        if (chunk > 0) {
            const float4* S4 = (const float4*)(g_S + (size_t)(b * NCHUNK + chunk) * HD * HD);
            for (int idx = tid; idx < 64 * 16; idx += 256) {
                int r = idx >> 4, c4 = idx & 15;
                *(float4*)&B0[r * SMSTR + c4 * 4] = S4[r * 16 + c4];
            }
        }
    }
    __syncthreads();

    float o[4][4];
    float p[4][4];
#pragma unroll
    for (int i = 0; i < 4; i++)
#pragma unroll
        for (int j = 0; j < 4; j++) o[i][j] = 0.0f;

    // ---- cross-chunk stage: o = gamma^(il+1) * Q @ S ----
    if (chunk > 0) {
#pragma unroll
        for (int i = 0; i < 4; i++)
#pragma unroll
            for (int j = 0; j < 4; j++) p[i][j] = 0.0f;
#pragma unroll 2
        for (int h = 0; h < 64; h += 4) {
            float4 qv[4], svv[4];
#pragma unroll
            for (int ii = 0; ii < 4; ii++)
                qv[ii] = *(const float4*)&Qs[(ty + 16 * ii) * SMSTR + h];
#pragma unroll
            for (int jj = 0; jj < 4; jj++)
                svv[jj] = *(const float4*)&B0[(tx + 16 * jj) * SMSTR + h];
#pragma unroll
            for (int ii = 0; ii < 4; ii++)
#pragma unroll
                for (int jj = 0; jj < 4; jj++) {
                    p[ii][jj] += qv[ii].x * svv[jj].x;
                    p[ii][jj] += qv[ii].y * svv[jj].y;
                    p[ii][jj] += qv[ii].z * svv[jj].z;
                    p[ii][jj] += qv[ii].w * svv[jj].w;
                }
        }
#pragma unroll
        for (int ii = 0; ii < 4; ii++) {
            float d = exp2f(LOG2_GAMMA * (float)(il0 + ty + 16 * ii + 1));
#pragma unroll
            for (int jj = 0; jj < 4; jj++) o[ii][jj] = d * p[ii][jj];
        }
    }

    // ---- within-chunk: 4 j-tiles ----
    for (int jt = 0; jt < 4; jt++) {
        const int j0 = chunk * CHUNKSZ + jt * 64;
        __syncthreads();
        // K tile row-major into B0
        {
            const float4* K4 = (const float4*)(g_K + (size_t)(b * SEQ + j0) * HD);
            for (int idx = tid; idx < 64 * 16; idx += 256) {
                int r = idx >> 4, c4 = idx & 15;
                *(float4*)&B0[r * SMSTR + c4 * 4] = K4[r * 16 + c4];
            }
        }
        // V tile transposed into Vt (4x4 float4 block transpose)
        {
            const float4* V4 = (const float4*)(g_V + (size_t)(b * SEQ + j0) * HD);
            float4 a0 = V4[(4 * jg + 0) * 16 + wg];
            float4 a1 = V4[(4 * jg + 1) * 16 + wg];
            float4 a2 = V4[(4 * jg + 2) * 16 + wg];
            float4 a3 = V4[(4 * jg + 3) * 16 + wg];
            *(float4*)&Vt[(4 * wg + 0) * SMSTR + 4 * jg] = make_float4(a0.x, a1.x, a2.x, a3.x);
            *(float4*)&Vt[(4 * wg + 1) * SMSTR + 4 * jg] = make_float4(a0.y, a1.y, a2.y, a3.y);
            *(float4*)&Vt[(4 * wg + 2) * SMSTR + 4 * jg] = make_float4(a0.z, a1.z, a2.z, a3.z);
            *(float4*)&Vt[(4 * wg + 3) * SMSTR + 4 * jg] = make_float4(a0.w, a1.w, a2.w, a3.w);
        }
        __syncthreads();

        // Stage 1: P = (Q K^T) * gamma^|i-j|
#pragma unroll
        for (int i = 0; i < 4; i++)
#pragma unroll
            for (int j = 0; j < 4; j++) p[i][j] = 0.0f;
#pragma unroll 2
        for (int h = 0; h < 64; h += 4) {
            float4 qv[4], kv[4];
#pragma unroll
            for (int ii = 0; ii < 4; ii++)
                qv[ii] = *(const float4*)&Qs[(ty + 16 * ii) * SMSTR + h];
#pragma unroll
            for (int jj = 0; jj < 4; jj++)
                kv[jj] = *(const float4*)&B0[(tx + 16 * jj) * SMSTR + h];
#pragma unroll
            for (int ii = 0; ii < 4; ii++)
#pragma unroll
                for (int jj = 0; jj < 4; jj++) {
                    p[ii][jj] += qv[ii].x * kv[jj].x;
                    p[ii][jj] += qv[ii].y * kv[jj].y;
                    p[ii][jj] += qv[ii].z * kv[jj].z;
                    p[ii][jj] += qv[ii].w * kv[jj].w;
                }
        }
#pragma unroll
        for (int ii = 0; ii < 4; ii++) {
            const int i = qbase + ty + 16 * ii;
#pragma unroll
            for (int jj = 0; jj < 4; jj++) {
                const int j = j0 + tx + 16 * jj;
                const float d = exp2f(LOG2_GAMMA * fabsf((float)(i - j)));
                Ps[(ty + 16 * ii) * SMSTR + tx + 16 * jj] = p[ii][jj] * d;
            }
        }
        __syncthreads();

        // Stage 2: O += P @ V
#pragma unroll 2
        for (int kj = 0; kj < 64; kj += 4) {
            float4 pv[4], vv[4];
#pragma unroll
            for (int ii = 0; ii < 4; ii++)
                pv[ii] = *(const float4*)&Ps[(ty + 16 * ii) * SMSTR + kj];
#pragma unroll
            for (int jj = 0; jj < 4; jj++)
                vv[jj] = *(const float4*)&Vt[(tx + 16 * jj) * SMSTR + kj];
#pragma unroll
            for (int ii = 0; ii < 4; ii++)
#pragma unroll
                for (int jj = 0; jj < 4; jj++) {
                    o[ii][jj] += pv[ii].x * vv[jj].x;
                    o[ii][jj] += pv[ii].y * vv[jj].y;
                    o[ii][jj] += pv[ii].z * vv[jj].z;
                    o[ii][jj] += pv[ii].w * vv[jj].w;
                }
        }
    }

    // Write output
#pragma unroll
    for (int ii = 0; ii < 4; ii++) {
        float* orow = out + (size_t)(b * SEQ + qbase + ty + 16 * ii) * HD;
#pragma unroll
        for (int jj = 0; jj < 4; jj++)
            orow[tx + 16 * jj] = o[ii][jj];
    }
}

// ---------------------------------------------------------------------------
extern "C" void kernel_launch(void* const* d_in, const int* in_sizes, int n_in,
                              void* d_out, int out_size) {
    const float* X  = (const float*)d_in[0];
    const float* WQ = (const float*)d_in[1];
    const float* WK = (const float*)d_in[2];
    const float* WV = (const float*)d_in[3];
    float* out = (float*)d_out;

    const size_t smA  = (size_t)(128 * SMSTR + 64 * SMSTR) * sizeof(float);  // 52224
    const size_t smR1 = (size_t)(2 * 64 * SMSTR) * sizeof(float);            // 34816
    const size_t smR3 = (size_t)(4 * 64 * SMSTR) * sizeof(float);            // 69632

    cudaFuncSetAttribute(qkv_kernel, cudaFuncAttributeMaxDynamicSharedMemorySize, (int)smA);
    cudaFuncSetAttribute(r1_kernel,  cudaFuncAttributeMaxDynamicSharedMemorySize, (int)smR1);
    cudaFuncSetAttribute(r3_kernel,  cudaFuncAttributeMaxDynamicSharedMemorySize, (int)smR3);

    tab_kernel<<<256, 256>>>();

    dim3 gridA(SEQ / 128, BATCH, 3);
    qkv_kernel<<<gridA, 256, smA>>>(X, WQ, WK, WV);

    dim3 gridR1(NCHUNK, BATCH);
    r1_kernel<<<gridR1, 256, smR1>>>();

    r2_kernel<<<BATCH, 256>>>();

    dim3 gridR3(SEQ / 64, BATCH);
    r3_kernel<<<gridR3, 256, smR3>>>(out);
}

// round 3
// speedup vs baseline: 4.6266x; 1.1327x over previous
#include <cuda_runtime.h>

#define BATCH 8
#define SEQ 2048
#define HID 512
#define HD 64
#define CHUNKSZ 256
#define NCHUNK (SEQ / CHUNKSZ)      // 8

// log2(0.96875)
#define LOG2_GAMMA (-0.04580368961312478f)

#define SMSTR 68   // smem row stride in floats (16B aligned, conflict-free)

typedef unsigned long long u64;

// ---------------------------------------------------------------------------
// f32x2 packed helpers (FFMA2 path — sm_103a)
// ---------------------------------------------------------------------------
__device__ __forceinline__ u64 bcast2(float x) {
    u64 r; asm("mov.b64 %0, {%1, %1};" : "=l"(r) : "f"(x)); return r;
}
__device__ __forceinline__ void fma2(u64& d, u64 a, u64 b) {
    asm("fma.rn.f32x2 %0, %1, %2, %3;" : "=l"(d) : "l"(a), "l"(b), "l"(d));
}
__device__ __forceinline__ u64 mul2(u64 a, u64 b) {
    u64 d; asm("mul.rn.f32x2 %0, %1, %2;" : "=l"(d) : "l"(a), "l"(b)); return d;
}
__device__ __forceinline__ float2 unpk(u64 v) {
    float lo, hi; asm("mov.b64 {%0, %1}, %2;" : "=f"(lo), "=f"(hi) : "l"(v));
    return make_float2(lo, hi);
}

// ---------------------------------------------------------------------------
// Device scratch
// ---------------------------------------------------------------------------
__device__ float g_Q[BATCH * SEQ * HD];
__device__ float g_K[BATCH * SEQ * HD];
__device__ float g_V[BATCH * SEQ * HD];
__device__ float g_A[BATCH * NCHUNK * HD * HD];   // per-chunk summaries, [v][h]
__device__ float g_S[BATCH * NCHUNK * HD * HD];   // scanned states,      [v][h]
__device__ float g_tab[SEQ * 128];                // per l: cosQ[32] sinQ[32] cosK[32] sinK[32]

// ---------------------------------------------------------------------------
// Table kernel: accurate xPos factors. 65536 threads.
// ---------------------------------------------------------------------------
__global__ void tab_kernel() {
    int tid = blockIdx.x * blockDim.x + threadIdx.x;
    int l = tid >> 5;
    int p = tid & 31;
    float sv = (2.0f * (float)p + 0.4f * (float)HD) / (1.4f * (float)HD);
    float pw = (float)l * (1.0f / 512.0f);
    float s = powf(sv, pw);
    float invf = powf(10000.0f, -(float)p * (1.0f / 32.0f));
    float si, co;
    sincosf((float)l * invf, &si, &co);
    float* t = g_tab + l * 128;
    t[p]      = co * s;
    t[32 + p] = si * s;
    t[64 + p] = co / s;
    t[96 + p] = si / s;
}

// ---------------------------------------------------------------------------
// Kernel A: QKV projection (f32x2) + table xPos epilogue.
// grid = (SEQ/128, BATCH, 3), block 256. Tile 128x64, per-thread 8 rows x 4 cols.
// Thread cols = 4tx..4tx+3 (two rotary pairs). smem: Xs[128][68] + Ws[64][68].
// ---------------------------------------------------------------------------
__global__ void __launch_bounds__(256, 2)
qkv_kernel(const float* __restrict__ X,
           const float* __restrict__ WQ,
           const float* __restrict__ WK,
           const float* __restrict__ WV) {
    extern __shared__ float sm[];
    float* Xs = sm;                    // [128][SMSTR]
    float* Ws = sm + 128 * SMSTR;      // [64][SMSTR] row-major

    const int g    = blockIdx.z;
    const int b    = blockIdx.y;
    const int row0 = blockIdx.x * 128;
    const int tid  = threadIdx.x;
    const int tx   = tid & 15;
    const int ty   = tid >> 4;

    const float* W = (g == 0) ? WQ : ((g == 1) ? WK : WV);

    u64 acc2[8][2];
#pragma unroll
    for (int i = 0; i < 8; i++) { acc2[i][0] = 0ull; acc2[i][1] = 0ull; }

    for (int k0 = 0; k0 < HID; k0 += 64) {
        __syncthreads();
        const float4* X4 = (const float4*)(X + (size_t)(b * SEQ + row0) * HID + k0);
        for (int idx = tid; idx < 128 * 16; idx += 256) {
            int r = idx >> 4, c4 = idx & 15;
            *(float4*)&Xs[r * SMSTR + c4 * 4] = X4[r * (HID / 4) + c4];
        }
        const float4* W4 = (const float4*)(W + (size_t)k0 * HD);
        for (int idx = tid; idx < 64 * 16; idx += 256) {
            int r = idx >> 4, c4 = idx & 15;
            *(float4*)&Ws[r * SMSTR + c4 * 4] = W4[r * (HD / 4) + c4];
        }
        __syncthreads();

        for (int kq = 0; kq < 64; kq += 4) {
            u64 w01[4], w23[4];
#pragma unroll
            for (int t = 0; t < 4; t++) {
                ulonglong2 w = *(const ulonglong2*)&Ws[(kq + t) * SMSTR + 4 * tx];
                w01[t] = w.x; w23[t] = w.y;
            }
#pragma unroll
            for (int i = 0; i < 8; i++) {
                float4 xv = *(const float4*)&Xs[(ty + 16 * i) * SMSTR + kq];
                u64 xx;
                xx = bcast2(xv.x); fma2(acc2[i][0], xx, w01[0]); fma2(acc2[i][1], xx, w23[0]);
                xx = bcast2(xv.y); fma2(acc2[i][0], xx, w01[1]); fma2(acc2[i][1], xx, w23[1]);
                xx = bcast2(xv.z); fma2(acc2[i][0], xx, w01[2]); fma2(acc2[i][1], xx, w23[2]);
                xx = bcast2(xv.w); fma2(acc2[i][0], xx, w01[3]); fma2(acc2[i][1], xx, w23[3]);
            }
        }
    }

    float* out = (g == 0) ? g_Q : ((g == 1) ? g_K : g_V);
#pragma unroll
    for (int i = 0; i < 8; i++) {
        const int l = row0 + ty + 16 * i;
        float* orow = out + (size_t)(b * SEQ + l) * HD;
        float2 a01 = unpk(acc2[i][0]);   // cols 4tx, 4tx+1  (pair p0 = 2tx)
        float2 a23 = unpk(acc2[i][1]);   // cols 4tx+2, 4tx+3 (pair p1 = 2tx+1)
        if (g == 2) {
            *(float4*)&orow[4 * tx] = make_float4(a01.x, a01.y, a23.x, a23.y);
        } else {
            const float* t = g_tab + l * 128 + (g == 1 ? 64 : 0);
            float c0 = t[2 * tx],     s0 = t[32 + 2 * tx];
            float c1 = t[2 * tx + 1], s1 = t[33 + 2 * tx];
            *(float4*)&orow[4 * tx] = make_float4(
                a01.x * c0 - a01.y * s0, a01.y * c0 + a01.x * s0,
                a23.x * c1 - a23.y * s1, a23.y * c1 + a23.x * s1);
        }
    }
}

// ---------------------------------------------------------------------------
// R1: per-chunk summary A_c[v][h] (f32x2 over h pairs).
// grid = (NCHUNK, BATCH), block 256. Thread: v rows ty+16ii, h cols 4tx..4tx+3.
// ---------------------------------------------------------------------------
__global__ void __launch_bounds__(256, 3)
r1_kernel() {
    extern __shared__ float sm[];
    float* Ks = sm;                 // [64][SMSTR], rows pre-scaled by decay
    float* Vs = sm + 64 * SMSTR;

    const int c = blockIdx.x;
    const int b = blockIdx.y;
    const int tid = threadIdx.x;
    const int tx = tid & 15;
    const int ty = tid >> 4;

    u64 acc2[4][2];
#pragma unroll
    for (int i = 0; i < 4; i++) { acc2[i][0] = 0ull; acc2[i][1] = 0ull; }

    for (int jt = 0; jt < 4; jt++) {
        const int j0 = c * CHUNKSZ + jt * 64;
        __syncthreads();
        const float4* K4 = (const float4*)(g_K + (size_t)(b * SEQ + j0) * HD);
        const float4* V4 = (const float4*)(g_V + (size_t)(b * SEQ + j0) * HD);
        for (int idx = tid; idx < 64 * 16; idx += 256) {
            int r = idx >> 4, c4 = idx & 15;
            float w = exp2f(LOG2_GAMMA * (float)(255 - (jt * 64 + r)));
            float4 kv = K4[r * 16 + c4];
            kv.x *= w; kv.y *= w; kv.z *= w; kv.w *= w;
            *(float4*)&Ks[r * SMSTR + c4 * 4] = kv;
            *(float4*)&Vs[r * SMSTR + c4 * 4] = V4[r * 16 + c4];
        }
        __syncthreads();

#pragma unroll 4
        for (int j = 0; j < 64; j++) {
            ulonglong2 kw = *(const ulonglong2*)&Ks[j * SMSTR + 4 * tx];
#pragma unroll
            for (int ii = 0; ii < 4; ii++) {
                u64 vv = bcast2(Vs[j * SMSTR + ty + 16 * ii]);
                fma2(acc2[ii][0], vv, kw.x);
                fma2(acc2[ii][1], vv, kw.y);
            }
        }
    }

    float* A = g_A + (size_t)(b * NCHUNK + c) * HD * HD;
#pragma unroll
    for (int ii = 0; ii < 4; ii++) {
        float2 a = unpk(acc2[ii][0]);
        float2 b2 = unpk(acc2[ii][1]);
        *(float4*)&A[(ty + 16 * ii) * HD + 4 * tx] = make_float4(a.x, a.y, b2.x, b2.y);
    }
}

// ---------------------------------------------------------------------------
// R2: elementwise parallel scan. grid = (16, BATCH) x 256 threads, 1 elem each.
// S_0 = 0,  S_c = gamma^256 * S_{c-1} + A_{c-1}
// ---------------------------------------------------------------------------
__global__ void r2_kernel() {
    const int b = blockIdx.y;
    const int e = blockIdx.x * 256 + threadIdx.x;   // 0..4095
    const float g256 = exp2f(LOG2_GAMMA * 256.0f);
    const float* A = g_A + (size_t)b * NCHUNK * HD * HD + e;
    float* S = g_S + (size_t)b * NCHUNK * HD * HD + e;
    float s = 0.0f;
#pragma unroll
    for (int c = 0; c < NCHUNK; c++) {
        S[c * HD * HD] = s;
        s = g256 * s + A[c * HD * HD];
    }
}

// ---------------------------------------------------------------------------
// R3: output (f32x2). grid = (SEQ/64, BATCH), block 256.
// Thread: rows ty+16ii, cols 4tx..4tx+3.
//   cross:  O = gamma^(il+1) * Q @ S_c   (S transposed in smem; skip chunk 0)
//   within: 4 j-tiles: P = (Q K^T)*decay (K transposed), O += P @ V (V row-major)
// smem: Qs + B0(St/Kt) + Vs + Ps, each [64][SMSTR]
// ---------------------------------------------------------------------------
__global__ void __launch_bounds__(256, 2)
r3_kernel(float* __restrict__ out) {
    extern __shared__ float sm[];
    float* Qs = sm;
    float* B0 = sm + 64 * SMSTR;
    float* Vs = sm + 2 * 64 * SMSTR;
    float* Ps = sm + 3 * 64 * SMSTR;

    const int b     = blockIdx.y;
    const int qbase = blockIdx.x * 64;
    const int chunk = qbase / CHUNKSZ;
    const int il0   = (blockIdx.x & 3) * 64;
    const int tid = threadIdx.x;
    const int tx  = tid & 15;
    const int ty  = tid >> 4;
    const int wg  = tid & 15;   // col group for transposes
    const int jg  = tid >> 4;   // row quad group

    // Load Q (row-major) and S_c transposed (St[h][v]) into B0
    {
        const float4* Q4 = (const float4*)(g_Q + (size_t)(b * SEQ + qbase) * HD);
        for (int idx = tid; idx < 64 * 16; idx += 256) {
            int r = idx >> 4, c4 = idx & 15;
            *(float4*)&Qs[r * SMSTR + c4 * 4] = Q4[r * 16 + c4];
        }
        if (chunk > 0) {
            const float4* S4 = (const float4*)(g_S + (size_t)(b * NCHUNK + chunk) * HD * HD);
            float4 a0 = S4[(4 * jg + 0) * 16 + wg];
            float4 a1 = S4[(4 * jg + 1) * 16 + wg];
            float4 a2 = S4[(4 * jg + 2) * 16 + wg];
            float4 a3 = S4[(4 * jg + 3) * 16 + wg];
            *(float4*)&B0[(4 * wg + 0) * SMSTR + 4 * jg] = make_float4(a0.x, a1.x, a2.x, a3.x);
            *(float4*)&B0[(4 * wg + 1) * SMSTR + 4 * jg] = make_float4(a0.y, a1.y, a2.y, a3.y);
            *(float4*)&B0[(4 * wg + 2) * SMSTR + 4 * jg] = make_float4(a0.z, a1.z, a2.z, a3.z);
            *(float4*)&B0[(4 * wg + 3) * SMSTR + 4 * jg] = make_float4(a0.w, a1.w, a2.w, a3.w);
        }
    }
    __syncthreads();

    u64 o2[4][2];
#pragma unroll
    for (int i = 0; i < 4; i++) { o2[i][0] = 0ull; o2[i][1] = 0ull; }

    // ---- cross-chunk: O = gamma^(il+1) * Q @ S ----
    if (chunk > 0) {
        u64 p2[4][2];
#pragma unroll
        for (int i = 0; i < 4; i++) { p2[i][0] = 0ull; p2[i][1] = 0ull; }
        for (int hq = 0; hq < 64; hq += 4) {
            u64 s01[4], s23[4];
#pragma unroll
            for (int t = 0; t < 4; t++) {
                ulonglong2 w = *(const ulonglong2*)&B0[(hq + t) * SMSTR + 4 * tx];
                s01[t] = w.x; s23[t] = w.y;
            }
#pragma unroll
            for (int ii = 0; ii < 4; ii++) {
                float4 qv = *(const float4*)&Qs[(ty + 16 * ii) * SMSTR + hq];
                u64 xx;
                xx = bcast2(qv.x); fma2(p2[ii][0], xx, s01[0]); fma2(p2[ii][1], xx, s23[0]);
                xx = bcast2(qv.y); fma2(p2[ii][0], xx, s01[1]); fma2(p2[ii][1], xx, s23[1]);
                xx = bcast2(qv.z); fma2(p2[ii][0], xx, s01[2]); fma2(p2[ii][1], xx, s23[2]);
                xx = bcast2(qv.w); fma2(p2[ii][0], xx, s01[3]); fma2(p2[ii][1], xx, s23[3]);
            }
        }
#pragma unroll
        for (int ii = 0; ii < 4; ii++) {
            u64 d = bcast2(exp2f(LOG2_GAMMA * (float)(il0 + ty + 16 * ii + 1)));
            o2[ii][0] = mul2(p2[ii][0], d);
            o2[ii][1] = mul2(p2[ii][1], d);
        }
    }

    // ---- within-chunk: 4 j-tiles ----
    for (int jt = 0; jt < 4; jt++) {
        const int j0 = chunk * CHUNKSZ + jt * 64;
        __syncthreads();
        // K tile transposed into B0: Kt[h][j]
        {
            const float4* K4 = (const float4*)(g_K + (size_t)(b * SEQ + j0) * HD);
            float4 a0 = K4[(4 * jg + 0) * 16 + wg];
            float4 a1 = K4[(4 * jg + 1) * 16 + wg];
            float4 a2 = K4[(4 * jg + 2) * 16 + wg];
            float4 a3 = K4[(4 * jg + 3) * 16 + wg];
            *(float4*)&B0[(4 * wg + 0) * SMSTR + 4 * jg] = make_float4(a0.x, a1.x, a2.x, a3.x);
            *(float4*)&B0[(4 * wg + 1) * SMSTR + 4 * jg] = make_float4(a0.y, a1.y, a2.y, a3.y);
            *(float4*)&B0[(4 * wg + 2) * SMSTR + 4 * jg] = make_float4(a0.z, a1.z, a2.z, a3.z);
            *(float4*)&B0[(4 * wg + 3) * SMSTR + 4 * jg] = make_float4(a0.w, a1.w, a2.w, a3.w);
        }
        // V tile row-major
        {
            const float4* V4 = (const float4*)(g_V + (size_t)(b * SEQ + j0) * HD);
            for (int idx = tid; idx < 64 * 16; idx += 256) {
                int r = idx >> 4, c4 = idx & 15;
                *(float4*)&Vs[r * SMSTR + c4 * 4] = V4[r * 16 + c4];
            }
        }
        __syncthreads();

        // Stage 1: P = Q K^T (pack over j)
        u64 p2[4][2];
#pragma unroll
        for (int i = 0; i < 4; i++) { p2[i][0] = 0ull; p2[i][1] = 0ull; }
        for (int hq = 0; hq < 64; hq += 4) {
            u64 k01[4], k23[4];
#pragma unroll
            for (int t = 0; t < 4; t++) {
                ulonglong2 w = *(const ulonglong2*)&B0[(hq + t) * SMSTR + 4 * tx];
                k01[t] = w.x; k23[t] = w.y;
            }
#pragma unroll
            for (int ii = 0; ii < 4; ii++) {
                float4 qv = *(const float4*)&Qs[(ty + 16 * ii) * SMSTR + hq];
                u64 xx;
                xx = bcast2(qv.x); fma2(p2[ii][0], xx, k01[0]); fma2(p2[ii][1], xx, k23[0]);
                xx = bcast2(qv.y); fma2(p2[ii][0], xx, k01[1]); fma2(p2[ii][1], xx, k23[1]);
                xx = bcast2(qv.z); fma2(p2[ii][0], xx, k01[2]); fma2(p2[ii][1], xx, k23[2]);
                xx = bcast2(qv.w); fma2(p2[ii][0], xx, k01[3]); fma2(p2[ii][1], xx, k23[3]);
            }
        }
        // decay + store P
#pragma unroll
        for (int ii = 0; ii < 4; ii++) {
            const int i = qbase + ty + 16 * ii;
            const int jb = j0 + 4 * tx;
            float2 a = unpk(p2[ii][0]);
            float2 b2 = unpk(p2[ii][1]);
            float d0 = exp2f(LOG2_GAMMA * fabsf((float)(i - jb)));
            float d1 = exp2f(LOG2_GAMMA * fabsf((float)(i - jb - 1)));
            float d2 = exp2f(LOG2_GAMMA * fabsf((float)(i - jb - 2)));
            float d3 = exp2f(LOG2_GAMMA * fabsf((float)(i - jb - 3)));
            *(float4*)&Ps[(ty + 16 * ii) * SMSTR + 4 * tx] =
                make_float4(a.x * d0, a.y * d1, b2.x * d2, b2.y * d3);
        }
        __syncthreads();

        // Stage 2: O += P @ V (pack over v)
        for (int kq = 0; kq < 64; kq += 4) {
            u64 v01[4], v23[4];
#pragma unroll
            for (int t = 0; t < 4; t++) {
                ulonglong2 w = *(const ulonglong2*)&Vs[(kq + t) * SMSTR + 4 * tx];
                v01[t] = w.x; v23[t] = w.y;
            }
#pragma unroll
            for (int ii = 0; ii < 4; ii++) {
                float4 pv = *(const float4*)&Ps[(ty + 16 * ii) * SMSTR + kq];
                u64 xx;
                xx = bcast2(pv.x); fma2(o2[ii][0], xx, v01[0]); fma2(o2[ii][1], xx, v23[0]);
                xx = bcast2(pv.y); fma2(o2[ii][0], xx, v01[1]); fma2(o2[ii][1], xx, v23[1]);
                xx = bcast2(pv.z); fma2(o2[ii][0], xx, v01[2]); fma2(o2[ii][1], xx, v23[2]);
                xx = bcast2(pv.w); fma2(o2[ii][0], xx, v01[3]); fma2(o2[ii][1], xx, v23[3]);
            }
        }
    }

    // Write output (contiguous float4 per thread)
#pragma unroll
    for (int ii = 0; ii < 4; ii++) {
        float* orow = out + (size_t)(b * SEQ + qbase + ty + 16 * ii) * HD;
        float2 a = unpk(o2[ii][0]);
        float2 b2 = unpk(o2[ii][1]);
        *(float4*)&orow[4 * tx] = make_float4(a.x, a.y, b2.x, b2.y);
    }
}

// ---------------------------------------------------------------------------
extern "C" void kernel_launch(void* const* d_in, const int* in_sizes, int n_in,
                              void* d_out, int out_size) {
    const float* X  = (const float*)d_in[0];
    const float* WQ = (const float*)d_in[1];
    const float* WK = (const float*)d_in[2];
    const float* WV = (const float*)d_in[3];
    float* out = (float*)d_out;

    const size_t smA  = (size_t)(128 * SMSTR + 64 * SMSTR) * sizeof(float);
    const size_t smR1 = (size_t)(2 * 64 * SMSTR) * sizeof(float);
    const size_t smR3 = (size_t)(4 * 64 * SMSTR) * sizeof(float);

    cudaFuncSetAttribute(qkv_kernel, cudaFuncAttributeMaxDynamicSharedMemorySize, (int)smA);
    cudaFuncSetAttribute(r1_kernel,  cudaFuncAttributeMaxDynamicSharedMemorySize, (int)smR1);
    cudaFuncSetAttribute(r3_kernel,  cudaFuncAttributeMaxDynamicSharedMemorySize, (int)smR3);

    tab_kernel<<<256, 256>>>();

    dim3 gridA(SEQ / 128, BATCH, 3);
    qkv_kernel<<<gridA, 256, smA>>>(X, WQ, WK, WV);

    dim3 gridR1(NCHUNK, BATCH);
    r1_kernel<<<gridR1, 256, smR1>>>();

    dim3 gridR2(16, BATCH);
    r2_kernel<<<gridR2, 256>>>();

    dim3 gridR3(SEQ / 64, BATCH);
    r3_kernel<<<gridR3, 256, smR3>>>(out);
}

// round 5
// speedup vs baseline: 6.5501x; 1.4158x over previous
#include <cuda_runtime.h>
#include <cuda_bf16.h>
#include <cstdint>

#define BATCH 8
#define SEQ 2048
#define HID 512
#define HD 64
#define CHUNKSZ 256
#define NCHUNK (SEQ / CHUNKSZ)      // 8

// log2(0.96875)
#define LOG2_GAMMA (-0.04580368961312478f)

#define SMSTR 68   // smem row stride in floats (retention kernels)

typedef unsigned long long u64;

// ---------------------------------------------------------------------------
// f32x2 packed helpers (FFMA2 path — retention kernels)
// ---------------------------------------------------------------------------
__device__ __forceinline__ u64 bcast2(float x) {
    u64 r; asm("mov.b64 %0, {%1, %1};" : "=l"(r) : "f"(x)); return r;
}
__device__ __forceinline__ void fma2(u64& d, u64 a, u64 b) {
    asm("fma.rn.f32x2 %0, %1, %2, %3;" : "=l"(d) : "l"(a), "l"(b), "l"(d));
}
__device__ __forceinline__ u64 mul2(u64 a, u64 b) {
    u64 d; asm("mul.rn.f32x2 %0, %1, %2;" : "=l"(d) : "l"(a), "l"(b)); return d;
}
__device__ __forceinline__ float2 unpk(u64 v) {
    float lo, hi; asm("mov.b64 {%0, %1}, %2;" : "=f"(lo), "=f"(hi) : "l"(v));
    return make_float2(lo, hi);
}

// ---------------------------------------------------------------------------
// Device scratch
// ---------------------------------------------------------------------------
__device__ float g_Q[BATCH * SEQ * HD];
__device__ float g_K[BATCH * SEQ * HD];
__device__ float g_V[BATCH * SEQ * HD];
__device__ float g_A[BATCH * NCHUNK * HD * HD];
__device__ float g_S[BATCH * NCHUNK * HD * HD];
__device__ float g_tab[SEQ * 128];                      // per l: cosQ[32] sinQ[32] cosK[32] sinK[32]
__device__ __nv_bfloat16 g_Wth[3 * HD * HID];           // W^T hi, [g][n][k]
__device__ __nv_bfloat16 g_Wtl[3 * HD * HID];           // W^T lo

// ---------------------------------------------------------------------------
// Table kernel: accurate xPos factors. 65536 threads.
// ---------------------------------------------------------------------------
__global__ void tab_kernel() {
    int tid = blockIdx.x * blockDim.x + threadIdx.x;
    int l = tid >> 5;
    int p = tid & 31;
    float sv = (2.0f * (float)p + 0.4f * (float)HD) / (1.4f * (float)HD);
    float pw = (float)l * (1.0f / 512.0f);
    float s = powf(sv, pw);
    float invf = powf(10000.0f, -(float)p * (1.0f / 32.0f));
    float si, co;
    sincosf((float)l * invf, &si, &co);
    float* t = g_tab + l * 128;
    t[p]      = co * s;
    t[32 + p] = si * s;
    t[64 + p] = co / s;
    t[96 + p] = si / s;
}

// ---------------------------------------------------------------------------
// convW: W[k,n] fp32 -> W^T[n,k] bf16 hi/lo for all 3 weight matrices.
// ---------------------------------------------------------------------------
__global__ void convw_kernel(const float* __restrict__ WQ,
                             const float* __restrict__ WK,
                             const float* __restrict__ WV) {
    int e = blockIdx.x * 256 + threadIdx.x;   // 0 .. 3*64*512-1
    if (e >= 3 * HD * HID) return;
    int g = e / (HD * HID);
    int r = e % (HD * HID);
    int n = r / HID;
    int k = r % HID;
    const float* W = (g == 0) ? WQ : ((g == 1) ? WK : WV);
    float x = W[k * HD + n];
    __nv_bfloat16 hb = __float2bfloat16_rn(x);
    float lf = x - __bfloat162float(hb);
    g_Wth[e] = hb;
    g_Wtl[e] = __float2bfloat16_rn(lf);
}

// ---------------------------------------------------------------------------
// mma.sync helpers (sm_80-class, legal for compute_103)
// ---------------------------------------------------------------------------
__device__ __forceinline__ void ldsm4(uint32_t* r, uint32_t addr) {
    asm volatile("ldmatrix.sync.aligned.m8n8.x4.shared.b16 {%0,%1,%2,%3}, [%4];"
                 : "=r"(r[0]), "=r"(r[1]), "=r"(r[2]), "=r"(r[3]) : "r"(addr));
}
__device__ __forceinline__ void mma16816(float* d, const uint32_t* a, const uint32_t* b) {
    asm volatile(
        "mma.sync.aligned.m16n8k16.row.col.f32.bf16.bf16.f32 "
        "{%0,%1,%2,%3}, {%4,%5,%6,%7}, {%8,%9}, {%0,%1,%2,%3};"
        : "+f"(d[0]), "+f"(d[1]), "+f"(d[2]), "+f"(d[3])
        : "r"(a[0]), "r"(a[1]), "r"(a[2]), "r"(a[3]), "r"(b[0]), "r"(b[1]));
}
__device__ __forceinline__ uint32_t pkbf2(float a, float b) {
    __nv_bfloat162 t = __floats2bfloat162_rn(a, b);
    return *(uint32_t*)&t;
}

// ---------------------------------------------------------------------------
// QKV projection via mma.sync bf16 (3-product hi/lo split) + xPos epilogue.
// grid = (SEQ/64, BATCH), 256 threads (8 warps = 2M x 4N).
// Block tile: M=64, N=192 (Q|K|V), K=512 in 8 chunks of 64.
// smem (bytes): AH[64][72]b16=9216, AL=9216, BH[192][72]=27648, BL=27648.
// ---------------------------------------------------------------------------
#define AH_O 0
#define AL_O 9216
#define BH_O 18432
#define BL_O 46080
#define QKV_SMEM 73728
#define BSTR 144   /* 72 bf16 * 2B */

__global__ void __launch_bounds__(256, 1)
qkvmma_kernel(const float* __restrict__ X) {
    extern __shared__ char smem[];
    const uint32_t sb = (uint32_t)__cvta_generic_to_shared(smem);
    const int tid  = threadIdx.x;
    const int wid  = tid >> 5;
    const int lane = tid & 31;
    const int b    = blockIdx.y;
    const int row0 = blockIdx.x * 64;

    const int mwarp = wid & 1;          // 0..1 -> rows 32*mwarp
    const int nwarp = wid >> 1;         // 0..3 -> cols 48*nwarp
    const int mbase = 32 * mwarp;
    const int nbase = 48 * nwarp;

    float d[2][6][4];
#pragma unroll
    for (int i = 0; i < 2; i++)
#pragma unroll
        for (int j = 0; j < 6; j++)
#pragma unroll
            for (int q = 0; q < 4; q++) d[i][j][q] = 0.0f;

    // precomputed ldmatrix lane address components
    const uint32_t a_row = (uint32_t)(lane & 15);
    const uint32_t a_kof = (uint32_t)((lane >> 4) << 3);
    const uint32_t b_row = (uint32_t)((lane & 7) + (((lane >> 4) & 1) << 3));
    const uint32_t b_kof = (uint32_t)(((lane >> 3) & 1) << 3);

    for (int c = 0; c < 8; c++) {
        const int k0 = c * 64;
        if (c) __syncthreads();

        // ---- stage A: X[row0..+63, k0..+63] -> bf16 hi/lo ----
        {
            const float4* X4 = (const float4*)(X + (size_t)(b * SEQ + row0) * HID + k0);
#pragma unroll
            for (int it = 0; it < 4; it++) {
                int idx = tid + 256 * it;
                int r = idx >> 4, c4 = idx & 15;
                float4 v = X4[r * (HID / 4) + c4];
                __nv_bfloat16 h0 = __float2bfloat16_rn(v.x);
                __nv_bfloat16 h1 = __float2bfloat16_rn(v.y);
                __nv_bfloat16 h2 = __float2bfloat16_rn(v.z);
                __nv_bfloat16 h3 = __float2bfloat16_rn(v.w);
                uint32_t hA = (uint32_t)*(uint16_t*)&h0 | ((uint32_t)*(uint16_t*)&h1 << 16);
                uint32_t hB = (uint32_t)*(uint16_t*)&h2 | ((uint32_t)*(uint16_t*)&h3 << 16);
                uint32_t off = (uint32_t)(r * BSTR + c4 * 8);
                *(uint2*)(smem + AH_O + off) = make_uint2(hA, hB);
                *(uint2*)(smem + AL_O + off) = make_uint2(
                    pkbf2(v.x - __bfloat162float(h0), v.y - __bfloat162float(h1)),
                    pkbf2(v.z - __bfloat162float(h2), v.w - __bfloat162float(h3)));
            }
        }
        // ---- stage B: W^T rows 0..191, cols k0..+63 ----
        {
#pragma unroll
            for (int it = 0; it < 6; it++) {
                int idx = tid + 256 * it;          // 0..1535
                int rr = idx >> 3, c8 = idx & 7;
                uint32_t off = (uint32_t)(rr * BSTR + c8 * 16);
                *(uint4*)(smem + BH_O + off) =
                    *(const uint4*)(g_Wth + (size_t)rr * HID + k0 + c8 * 8);
                *(uint4*)(smem + BL_O + off) =
                    *(const uint4*)(g_Wtl + (size_t)rr * HID + k0 + c8 * 8);
            }
        }
        __syncthreads();

#pragma unroll
        for (int kk = 0; kk < 64; kk += 16) {
            uint32_t ah[2][4], al[2][4], bh[3][4], bl[3][4];
#pragma unroll
            for (int mi = 0; mi < 2; mi++) {
                uint32_t ao = (uint32_t)((mbase + mi * 16 + a_row) * BSTR + (kk + a_kof) * 2);
                ldsm4(ah[mi], sb + AH_O + ao);
                ldsm4(al[mi], sb + AL_O + ao);
            }
#pragma unroll
            for (int ng = 0; ng < 3; ng++) {
                uint32_t bo = (uint32_t)((nbase + ng * 16 + b_row) * BSTR + (kk + b_kof) * 2);
                ldsm4(bh[ng], sb + BH_O + bo);
                ldsm4(bl[ng], sb + BL_O + bo);
            }
#pragma unroll
            for (int mi = 0; mi < 2; mi++)
#pragma unroll
                for (int nj = 0; nj < 6; nj++) {
                    const uint32_t* Bh = &bh[nj >> 1][(nj & 1) * 2];
                    const uint32_t* Bl = &bl[nj >> 1][(nj & 1) * 2];
                    mma16816(d[mi][nj], ah[mi], Bh);
                    mma16816(d[mi][nj], ah[mi], Bl);
                    mma16816(d[mi][nj], al[mi], Bh);
                }
        }
    }

    // ---- epilogue: rotary for Q/K, direct for V ----
#pragma unroll
    for (int mi = 0; mi < 2; mi++) {
        const int r0 = row0 + mbase + mi * 16 + (lane >> 2);
#pragma unroll
        for (int nj = 0; nj < 6; nj++) {
            const int cgl = nbase + nj * 8 + (lane & 3) * 2;   // 0..190, even
            const int g = cgl >> 6;
            const int hd = cgl & 63;
            const int p = hd >> 1;
            float* base = (g == 0) ? g_Q : ((g == 1) ? g_K : g_V);
#pragma unroll
            for (int rh = 0; rh < 2; rh++) {
                const int r = r0 + rh * 8;
                float e = d[mi][nj][rh * 2];
                float o = d[mi][nj][rh * 2 + 1];
                float* dst = base + (size_t)(b * SEQ + r) * HD + hd;
                if (g < 2) {
                    const float* t = g_tab + r * 128 + (g << 6);
                    float cc = t[p], ss = t[32 + p];
                    *(float2*)dst = make_float2(e * cc - o * ss, o * cc + e * ss);
                } else {
                    *(float2*)dst = make_float2(e, o);
                }
            }
        }
    }
}

// ---------------------------------------------------------------------------
// R1: per-chunk summary A_c[v][h] (f32x2 over h pairs).
// ---------------------------------------------------------------------------
__global__ void __launch_bounds__(256, 3)
r1_kernel() {
    extern __shared__ float sm[];
    float* Ks = sm;
    float* Vs = sm + 64 * SMSTR;

    const int c = blockIdx.x;
    const int b = blockIdx.y;
    const int tid = threadIdx.x;
    const int tx = tid & 15;
    const int ty = tid >> 4;

    u64 acc2[4][2];
#pragma unroll
    for (int i = 0; i < 4; i++) { acc2[i][0] = 0ull; acc2[i][1] = 0ull; }

    for (int jt = 0; jt < 4; jt++) {
        const int j0 = c * CHUNKSZ + jt * 64;
        __syncthreads();
        const float4* K4 = (const float4*)(g_K + (size_t)(b * SEQ + j0) * HD);
        const float4* V4 = (const float4*)(g_V + (size_t)(b * SEQ + j0) * HD);
        for (int idx = tid; idx < 64 * 16; idx += 256) {
            int r = idx >> 4, c4 = idx & 15;
            float w = exp2f(LOG2_GAMMA * (float)(255 - (jt * 64 + r)));
            float4 kv = K4[r * 16 + c4];
            kv.x *= w; kv.y *= w; kv.z *= w; kv.w *= w;
            *(float4*)&Ks[r * SMSTR + c4 * 4] = kv;
            *(float4*)&Vs[r * SMSTR + c4 * 4] = V4[r * 16 + c4];
        }
        __syncthreads();

#pragma unroll 4
        for (int j = 0; j < 64; j++) {
            ulonglong2 kw = *(const ulonglong2*)&Ks[j * SMSTR + 4 * tx];
#pragma unroll
            for (int ii = 0; ii < 4; ii++) {
                u64 vv = bcast2(Vs[j * SMSTR + ty + 16 * ii]);
                fma2(acc2[ii][0], vv, kw.x);
                fma2(acc2[ii][1], vv, kw.y);
            }
        }
    }

    float* A = g_A + (size_t)(b * NCHUNK + c) * HD * HD;
#pragma unroll
    for (int ii = 0; ii < 4; ii++) {
        float2 a = unpk(acc2[ii][0]);
        float2 b2 = unpk(acc2[ii][1]);
        *(float4*)&A[(ty + 16 * ii) * HD + 4 * tx] = make_float4(a.x, a.y, b2.x, b2.y);
    }
}

// ---------------------------------------------------------------------------
// R2: elementwise parallel scan.
// ---------------------------------------------------------------------------
__global__ void r2_kernel() {
    const int b = blockIdx.y;
    const int e = blockIdx.x * 256 + threadIdx.x;
    const float g256 = exp2f(LOG2_GAMMA * 256.0f);
    const float* A = g_A + (size_t)b * NCHUNK * HD * HD + e;
    float* S = g_S + (size_t)b * NCHUNK * HD * HD + e;
    float s = 0.0f;
#pragma unroll
    for (int c = 0; c < NCHUNK; c++) {
        S[c * HD * HD] = s;
        s = g256 * s + A[c * HD * HD];
    }
}

// ---------------------------------------------------------------------------
// R3: output (f32x2).
// ---------------------------------------------------------------------------
__global__ void __launch_bounds__(256, 2)
r3_kernel(float* __restrict__ out) {
    extern __shared__ float sm[];
    float* Qs = sm;
    float* B0 = sm + 64 * SMSTR;
    float* Vs = sm + 2 * 64 * SMSTR;
    float* Ps = sm + 3 * 64 * SMSTR;

    const int b     = blockIdx.y;
    const int qbase = blockIdx.x * 64;
    const int chunk = qbase / CHUNKSZ;
    const int il0   = (blockIdx.x & 3) * 64;
    const int tid = threadIdx.x;
    const int tx  = tid & 15;
    const int ty  = tid >> 4;
    const int wg  = tid & 15;
    const int jg  = tid >> 4;

    {
        const float4* Q4 = (const float4*)(g_Q + (size_t)(b * SEQ + qbase) * HD);
        for (int idx = tid; idx < 64 * 16; idx += 256) {
            int r = idx >> 4, c4 = idx & 15;
            *(float4*)&Qs[r * SMSTR + c4 * 4] = Q4[r * 16 + c4];
        }
        if (chunk > 0) {
            const float4* S4 = (const float4*)(g_S + (size_t)(b * NCHUNK + chunk) * HD * HD);
            float4 a0 = S4[(4 * jg + 0) * 16 + wg];
            float4 a1 = S4[(4 * jg + 1) * 16 + wg];
            float4 a2 = S4[(4 * jg + 2) * 16 + wg];
            float4 a3 = S4[(4 * jg + 3) * 16 + wg];
            *(float4*)&B0[(4 * wg + 0) * SMSTR + 4 * jg] = make_float4(a0.x, a1.x, a2.x, a3.x);
            *(float4*)&B0[(4 * wg + 1) * SMSTR + 4 * jg] = make_float4(a0.y, a1.y, a2.y, a3.y);
            *(float4*)&B0[(4 * wg + 2) * SMSTR + 4 * jg] = make_float4(a0.z, a1.z, a2.z, a3.z);
            *(float4*)&B0[(4 * wg + 3) * SMSTR + 4 * jg] = make_float4(a0.w, a1.w, a2.w, a3.w);
        }
    }
    __syncthreads();

    u64 o2[4][2];
#pragma unroll
    for (int i = 0; i < 4; i++) { o2[i][0] = 0ull; o2[i][1] = 0ull; }

    if (chunk > 0) {
        u64 p2[4][2];
#pragma unroll
        for (int i = 0; i < 4; i++) { p2[i][0] = 0ull; p2[i][1] = 0ull; }
        for (int hq = 0; hq < 64; hq += 4) {
            u64 s01[4], s23[4];
#pragma unroll
            for (int t = 0; t < 4; t++) {
                ulonglong2 w = *(const ulonglong2*)&B0[(hq + t) * SMSTR + 4 * tx];
                s01[t] = w.x; s23[t] = w.y;
            }
#pragma unroll
            for (int ii = 0; ii < 4; ii++) {
                float4 qv = *(const float4*)&Qs[(ty + 16 * ii) * SMSTR + hq];
                u64 xx;
                xx = bcast2(qv.x); fma2(p2[ii][0], xx, s01[0]); fma2(p2[ii][1], xx, s23[0]);
                xx = bcast2(qv.y); fma2(p2[ii][0], xx, s01[1]); fma2(p2[ii][1], xx, s23[1]);
                xx = bcast2(qv.z); fma2(p2[ii][0], xx, s01[2]); fma2(p2[ii][1], xx, s23[2]);
                xx = bcast2(qv.w); fma2(p2[ii][0], xx, s01[3]); fma2(p2[ii][1], xx, s23[3]);
            }
        }
#pragma unroll
        for (int ii = 0; ii < 4; ii++) {
            u64 dd = bcast2(exp2f(LOG2_GAMMA * (float)(il0 + ty + 16 * ii + 1)));
            o2[ii][0] = mul2(p2[ii][0], dd);
            o2[ii][1] = mul2(p2[ii][1], dd);
        }
    }

    for (int jt = 0; jt < 4; jt++) {
        const int j0 = chunk * CHUNKSZ + jt * 64;
        __syncthreads();
        {
            const float4* K4 = (const float4*)(g_K + (size_t)(b * SEQ + j0) * HD);
            float4 a0 = K4[(4 * jg + 0) * 16 + wg];
            float4 a1 = K4[(4 * jg + 1) * 16 + wg];
            float4 a2 = K4[(4 * jg + 2) * 16 + wg];
            float4 a3 = K4[(4 * jg + 3) * 16 + wg];
            *(float4*)&B0[(4 * wg + 0) * SMSTR + 4 * jg] = make_float4(a0.x, a1.x, a2.x, a3.x);
            *(float4*)&B0[(4 * wg + 1) * SMSTR + 4 * jg] = make_float4(a0.y, a1.y, a2.y, a3.y);
            *(float4*)&B0[(4 * wg + 2) * SMSTR + 4 * jg] = make_float4(a0.z, a1.z, a2.z, a3.z);
            *(float4*)&B0[(4 * wg + 3) * SMSTR + 4 * jg] = make_float4(a0.w, a1.w, a2.w, a3.w);
        }
        {
            const float4* V4 = (const float4*)(g_V + (size_t)(b * SEQ + j0) * HD);
            for (int idx = tid; idx < 64 * 16; idx += 256) {
                int r = idx >> 4, c4 = idx & 15;
                *(float4*)&Vs[r * SMSTR + c4 * 4] = V4[r * 16 + c4];
            }
        }
        __syncthreads();

        u64 p2[4][2];
#pragma unroll
        for (int i = 0; i < 4; i++) { p2[i][0] = 0ull; p2[i][1] = 0ull; }
        for (int hq = 0; hq < 64; hq += 4) {
            u64 k01[4], k23[4];
#pragma unroll
            for (int t = 0; t < 4; t++) {
                ulonglong2 w = *(const ulonglong2*)&B0[(hq + t) * SMSTR + 4 * tx];
                k01[t] = w.x; k23[t] = w.y;
            }
#pragma unroll
            for (int ii = 0; ii < 4; ii++) {
                float4 qv = *(const float4*)&Qs[(ty + 16 * ii) * SMSTR + hq];
                u64 xx;
                xx = bcast2(qv.x); fma2(p2[ii][0], xx, k01[0]); fma2(p2[ii][1], xx, k23[0]);
                xx = bcast2(qv.y); fma2(p2[ii][0], xx, k01[1]); fma2(p2[ii][1], xx, k23[1]);
                xx = bcast2(qv.z); fma2(p2[ii][0], xx, k01[2]); fma2(p2[ii][1], xx, k23[2]);
                xx = bcast2(qv.w); fma2(p2[ii][0], xx, k01[3]); fma2(p2[ii][1], xx, k23[3]);
            }
        }
#pragma unroll
        for (int ii = 0; ii < 4; ii++) {
            const int i = qbase + ty + 16 * ii;
            const int jb = j0 + 4 * tx;
            float2 a = unpk(p2[ii][0]);
            float2 b2 = unpk(p2[ii][1]);
            float d0 = exp2f(LOG2_GAMMA * fabsf((float)(i - jb)));
            float d1 = exp2f(LOG2_GAMMA * fabsf((float)(i - jb - 1)));
            float d2 = exp2f(LOG2_GAMMA * fabsf((float)(i - jb - 2)));
            float d3 = exp2f(LOG2_GAMMA * fabsf((float)(i - jb - 3)));
            *(float4*)&Ps[(ty + 16 * ii) * SMSTR + 4 * tx] =
                make_float4(a.x * d0, a.y * d1, b2.x * d2, b2.y * d3);
        }
        __syncthreads();

        for (int kq = 0; kq < 64; kq += 4) {
            u64 v01[4], v23[4];
#pragma unroll
            for (int t = 0; t < 4; t++) {
                ulonglong2 w = *(const ulonglong2*)&Vs[(kq + t) * SMSTR + 4 * tx];
                v01[t] = w.x; v23[t] = w.y;
            }
#pragma unroll
            for (int ii = 0; ii < 4; ii++) {
                float4 pv = *(const float4*)&Ps[(ty + 16 * ii) * SMSTR + kq];
                u64 xx;
                xx = bcast2(pv.x); fma2(o2[ii][0], xx, v01[0]); fma2(o2[ii][1], xx, v23[0]);
                xx = bcast2(pv.y); fma2(o2[ii][0], xx, v01[1]); fma2(o2[ii][1], xx, v23[1]);
                xx = bcast2(pv.z); fma2(o2[ii][0], xx, v01[2]); fma2(o2[ii][1], xx, v23[2]);
                xx = bcast2(pv.w); fma2(o2[ii][0], xx, v01[3]); fma2(o2[ii][1], xx, v23[3]);
            }
        }
    }

#pragma unroll
    for (int ii = 0; ii < 4; ii++) {
        float* orow = out + (size_t)(b * SEQ + qbase + ty + 16 * ii) * HD;
        float2 a = unpk(o2[ii][0]);
        float2 b2 = unpk(o2[ii][1]);
        *(float4*)&orow[4 * tx] = make_float4(a.x, a.y, b2.x, b2.y);
    }
}

// ---------------------------------------------------------------------------
extern "C" void kernel_launch(void* const* d_in, const int* in_sizes, int n_in,
                              void* d_out, int out_size) {
    const float* X  = (const float*)d_in[0];
    const float* WQ = (const float*)d_in[1];
    const float* WK = (const float*)d_in[2];
    const float* WV = (const float*)d_in[3];
    float* out = (float*)d_out;

    const size_t smR1 = (size_t)(2 * 64 * SMSTR) * sizeof(float);
    const size_t smR3 = (size_t)(4 * 64 * SMSTR) * sizeof(float);

    cudaFuncSetAttribute(qkvmma_kernel, cudaFuncAttributeMaxDynamicSharedMemorySize, QKV_SMEM);
    cudaFuncSetAttribute(r1_kernel, cudaFuncAttributeMaxDynamicSharedMemorySize, (int)smR1);
    cudaFuncSetAttribute(r3_kernel, cudaFuncAttributeMaxDynamicSharedMemorySize, (int)smR3);

    tab_kernel<<<256, 256>>>();
    convw_kernel<<<(3 * HD * HID + 255) / 256, 256>>>(WQ, WK, WV);

    dim3 gridA(SEQ / 64, BATCH);
    qkvmma_kernel<<<gridA, 256, QKV_SMEM>>>(X);

    dim3 gridR1(NCHUNK, BATCH);
    r1_kernel<<<gridR1, 256, smR1>>>();

    dim3 gridR2(16, BATCH);
    r2_kernel<<<gridR2, 256>>>();

    dim3 gridR3(SEQ / 64, BATCH);
    r3_kernel<<<gridR3, 256, smR3>>>(out);
}